// round 13
// baseline (speedup 1.0000x reference)
#include <cuda_runtime.h>
#include <cuda_fp16.h>
#include <cstdint>

// ----------------------------------------------------------------------------
// Coembedding via warp-level plain-fp16 mma.sync (fp32 accumulate).
// R12: 475us, rel_err 6.52e-4 (error budget now ~spent). This round widens
// the GEMM geometry for efficiency: CTA 256x128, 8 warps, warp tile 64x64
// (LDSM:MMA 0.375 -> 0.25, 128-reg accumulators for deeper tensor ILP).
// Pipeline/swizzle/fragment maps identical to the validated R10-R12 core.
// Shapes: N=4096, M=8192, MOL=768, PROT=1280, D=1024.
// ----------------------------------------------------------------------------

// ======================= PTX helpers (compute_100-safe) =====================
__device__ __forceinline__ uint32_t smem_u32(const void* p) {
    uint32_t a;
    asm("{ .reg .u64 t; cvta.to.shared.u64 t, %1; cvt.u32.u64 %0, t; }"
        : "=r"(a) : "l"(p));
    return a;
}
__device__ __forceinline__ void cp_async16(uint32_t dst, const void* src) {
    asm volatile("cp.async.cg.shared.global [%0], [%1], 16;\n" :: "r"(dst), "l"(src));
}
__device__ __forceinline__ void cp_commit() {
    asm volatile("cp.async.commit_group;\n");
}
template <int N> __device__ __forceinline__ void cp_wait() {
    asm volatile("cp.async.wait_group %0;\n" :: "n"(N));
}
__device__ __forceinline__ void ldsm_x4(uint32_t& r0, uint32_t& r1,
                                        uint32_t& r2, uint32_t& r3, uint32_t addr) {
    asm volatile("ldmatrix.sync.aligned.m8n8.x4.shared.b16 {%0,%1,%2,%3}, [%4];"
                 : "=r"(r0), "=r"(r1), "=r"(r2), "=r"(r3) : "r"(addr));
}
__device__ __forceinline__ void mma_fp16(float* c, const uint32_t* a, const uint32_t* b) {
    asm volatile(
        "mma.sync.aligned.m16n8k16.row.col.f32.f16.f16.f32 "
        "{%0,%1,%2,%3}, {%4,%5,%6,%7}, {%8,%9}, {%0,%1,%2,%3};"
        : "+f"(c[0]), "+f"(c[1]), "+f"(c[2]), "+f"(c[3])
        : "r"(a[0]), "r"(a[1]), "r"(a[2]), "r"(a[3]), "r"(b[0]), "r"(b[1]));
}

// ======================= scratch (allocation-free rule) =====================
__device__ __half g_molA [4096u * 768u];
__device__ __half g_Wm1B [1024u * 768u];
__device__ __half g_Wm2B [1024u * 1024u];
__device__ __half g_protA[8192u * 1280u];
__device__ __half g_Wp1B [1024u * 1280u];
__device__ __half g_Wp2B [1024u * 1024u];
__device__ __half g_HmA  [4096u * 1024u];
__device__ __half g_HpA  [8192u * 1024u];
__device__ __half g_MPnB [4096u * 1024u];
__device__ __half g_PPnA [8192u * 1024u];
__device__ float g_MP32[4096u * 1024u];
__device__ float g_PP32[8192u * 1024u];

// ======================= conversion kernels =================================
__global__ __launch_bounds__(256) void tofp16_kernel(
    const float* __restrict__ X, __half* __restrict__ Y, int n4)
{
    int i = blockIdx.x * 256 + threadIdx.x;
    if (i < n4) {
        float4 v = ((const float4*)X)[i];
        ((__half2*)Y)[2 * i]     = __floats2half2_rn(v.x, v.y);
        ((__half2*)Y)[2 * i + 1] = __floats2half2_rn(v.z, v.w);
    }
}

// fp32 [R,D] -> L2-normalize row (eps clamp) -> fp16 [R,D].
__global__ __launch_bounds__(256) void normhalf_kernel(
    const float* __restrict__ X, __half* __restrict__ Y, int D)
{
    const float* x = X + (size_t)blockIdx.x * D;
    __half* y = Y + (size_t)blockIdx.x * D;
    const int tid = threadIdx.x;

    float s = 0.0f;
    for (int i = tid * 4; i < D; i += 1024) {
        float4 v = *(const float4*)(x + i);
        s = fmaf(v.x, v.x, s); s = fmaf(v.y, v.y, s);
        s = fmaf(v.z, v.z, s); s = fmaf(v.w, v.w, s);
    }
    #pragma unroll
    for (int o = 16; o > 0; o >>= 1) s += __shfl_xor_sync(0xffffffff, s, o);
    __shared__ float red[8]; __shared__ float s_inv;
    if ((tid & 31) == 0) red[tid >> 5] = s;
    __syncthreads();
    if (tid == 0) {
        float t = 0.0f;
        #pragma unroll
        for (int w = 0; w < 8; w++) t += red[w];
        s_inv = 1.0f / fmaxf(sqrtf(t), 1e-8f);
    }
    __syncthreads();
    const float inv = s_inv;
    for (int i = tid * 4; i < D; i += 1024) {
        float4 v = *(const float4*)(x + i);
        *(__half2*)(y + i)     = __floats2half2_rn(v.x * inv, v.y * inv);
        *(__half2*)(y + i + 2) = __floats2half2_rn(v.z * inv, v.w * inv);
    }
}

// ======================= mma.sync fp16 GEMM =================================
// C[M,N] = A[M,K] @ B[N,K]^T (fp16, K-major), fp32 accumulate + epilogue.
// CTA tile 256x128, K-chunk 64 fp16 (128 B rows, SW128), 3 stages,
// 256 threads / 8 warps in a 4(M) x 2(N) grid; warp tile 64x64.
// Requires M % 256 == 0, N % 128 == 0, K % 64 == 0 (true for all call sites).
#define A_TILE_B 32768                 // A tile: 256 rows x 128 B
#define B_TILE_B 16384                 // B tile: 128 rows x 128 B
#define STAGE_B  (A_TILE_B + B_TILE_B) // 48 KB
#define GSMEM_TOTAL (3 * STAGE_B)      // 147456 B dynamic smem

template <bool RELU, bool HAS_BIAS, bool HAS_SCALE, bool HALF_OUT>
__global__ __launch_bounds__(256) void gemm_mma(
    const __half* __restrict__ A, const __half* __restrict__ B,
    const float* __restrict__ bias, const float* __restrict__ tempPtr,
    void* __restrict__ Cv, int M, int N, int K)
{
    extern __shared__ char smem[];
    const uint32_t sbase = smem_u32(smem);
    const int tid = threadIdx.x;
    const int lane = tid & 31;
    const int wid = tid >> 5;
    const int warpM = wid & 3;          // 4 warps along M (64 rows each)
    const int warpN = wid >> 2;         // 2 warps along N (64 cols each)

    const int rowBase = blockIdx.y * 256;
    const int colBase = blockIdx.x * 128;
    const size_t stride = (size_t)K * 2;            // bytes per row (A and B)
    const char* Ab = (const char*)A + (size_t)rowBase * stride;
    const char* Bb = (const char*)B + (size_t)colBase * stride;
    const int T = K / 64;                           // K-chunks

    // ---- cp.async tile loader: A 2048 chunks (8/thread) + B 1024 (4/thread).
    auto load_tile = [&](int t, int s) {
        const uint32_t sA = sbase + s * STAGE_B;
        const uint32_t sB = sA + A_TILE_B;
        const size_t kb = (size_t)t * 128;
        #pragma unroll
        for (int i = 0; i < 8; i++) {
            int id = tid + i * 256;
            int row = id >> 3;
            int c = (id & 7) << 4;
            uint32_t doff = row * 128 + (c ^ ((row & 7) << 4));
            cp_async16(sA + doff, Ab + (size_t)row * stride + kb + c);
        }
        #pragma unroll
        for (int i = 0; i < 4; i++) {
            int id = tid + i * 256;
            int row = id >> 3;
            int c = (id & 7) << 4;
            uint32_t doff = row * 128 + (c ^ ((row & 7) << 4));
            cp_async16(sB + doff, Bb + (size_t)row * stride + kb + c);
        }
        cp_commit();
    };

    // ---- ldmatrix lane-address components (canonical m16n8k16 layouts).
    const int aRowL = lane & 15;
    const uint32_t aHalf = (uint32_t)((lane >> 4) << 4);   // 0 or 16 bytes
    uint32_t aRowOff[4], aXor[4];
    #pragma unroll
    for (int mi = 0; mi < 4; mi++) {
        int r = warpM * 64 + mi * 16 + aRowL;
        aRowOff[mi] = r * 128;
        aXor[mi] = (r & 7) << 4;
    }
    const int bRowL = (lane & 7) + ((lane >> 4) << 3);
    const uint32_t bHalf = (uint32_t)(((lane >> 3) & 1) << 4);
    uint32_t bRowOff[4], bXor[4];
    #pragma unroll
    for (int p = 0; p < 4; p++) {
        int r = warpN * 64 + p * 16 + bRowL;
        bRowOff[p] = r * 128;
        bXor[p] = (r & 7) << 4;
    }

    float acc[4][8][4];
    #pragma unroll
    for (int mi = 0; mi < 4; mi++)
        #pragma unroll
        for (int ni = 0; ni < 8; ni++)
            #pragma unroll
            for (int u = 0; u < 4; u++) acc[mi][ni][u] = 0.0f;

    // ---- prologue: stages 0,1.
    load_tile(0, 0);
    load_tile(1, 1);

    for (int t = 0; t < T; t++) {
        cp_wait<1>();            // tile t's group complete
        __syncthreads();         // everyone done reading stage (t+2)%3
        if (t + 2 < T) load_tile(t + 2, (t + 2) % 3);
        else           cp_commit();   // keep group ledger uniform in the tail

        const uint32_t sA = sbase + (t % 3) * STAGE_B;
        const uint32_t sB = sA + A_TILE_B;

        #pragma unroll
        for (int ks = 0; ks < 4; ks++) {           // 4 x k16 per 64-elem chunk
            const uint32_t kA = ks * 32 + aHalf;   // byte col in 128B row
            const uint32_t kB = ks * 32 + bHalf;
            uint32_t a[4][4];
            uint32_t b[8][2];
            #pragma unroll
            for (int mi = 0; mi < 4; mi++)
                ldsm_x4(a[mi][0], a[mi][1], a[mi][2], a[mi][3],
                        sA + aRowOff[mi] + (kA ^ aXor[mi]));
            #pragma unroll
            for (int p = 0; p < 4; p++) {
                uint32_t r0, r1, r2, r3;
                ldsm_x4(r0, r1, r2, r3, sB + bRowOff[p] + (kB ^ bXor[p]));
                b[2 * p][0] = r0; b[2 * p][1] = r1;
                b[2 * p + 1][0] = r2; b[2 * p + 1][1] = r3;
            }
            #pragma unroll
            for (int mi = 0; mi < 4; mi++)
                #pragma unroll
                for (int ni = 0; ni < 8; ni++)
                    mma_fp16(acc[mi][ni], a[mi], b[ni]);
        }
    }

    // ---- epilogue: bias / ReLU / scale; fp32 or fp16 stores.
    float alpha = 1.0f;
    if (HAS_SCALE) alpha = 1.0f / (*tempPtr);
    const int orow0 = rowBase + warpM * 64;
    const int ocol0 = colBase + warpN * 64;
    const int qr = lane >> 2;
    const int qc = (lane & 3) << 1;

    #pragma unroll
    for (int mi = 0; mi < 4; mi++) {
        const int r0 = orow0 + mi * 16 + qr;
        #pragma unroll
        for (int ni = 0; ni < 8; ni++) {
            const int cc = ocol0 + ni * 8 + qc;
            float b0 = 0.0f, b1 = 0.0f;
            if (HAS_BIAS) { b0 = bias[cc]; b1 = bias[cc + 1]; }
            float v0 = acc[mi][ni][0] + b0;
            float v1 = acc[mi][ni][1] + b1;
            float v2 = acc[mi][ni][2] + b0;
            float v3 = acc[mi][ni][3] + b1;
            if (RELU) {
                v0 = fmaxf(v0, 0.0f); v1 = fmaxf(v1, 0.0f);
                v2 = fmaxf(v2, 0.0f); v3 = fmaxf(v3, 0.0f);
            }
            if (HAS_SCALE) { v0 *= alpha; v1 *= alpha; v2 *= alpha; v3 *= alpha; }
            if (HALF_OUT) {
                __half* Ch = (__half*)Cv;
                *(__half2*)(Ch + (size_t)r0 * N + cc)       = __floats2half2_rn(v0, v1);
                *(__half2*)(Ch + (size_t)(r0 + 8) * N + cc) = __floats2half2_rn(v2, v3);
            } else {
                float* C = (float*)Cv;
                float2 o0 = {v0, v1}, o1 = {v2, v3};
                *(float2*)(C + (size_t)r0 * N + cc) = o0;
                *(float2*)(C + (size_t)(r0 + 8) * N + cc) = o1;
            }
        }
    }
}

// ======================= host wiring ========================================
extern "C" void kernel_launch(void* const* d_in, const int* in_sizes, int n_in,
                              void* d_out, int out_size)
{
    const float* molecule = (const float*)d_in[0];
    const float* protein  = (const float*)d_in[1];
    const float* Wm1 = (const float*)d_in[2];
    const float* bm1 = (const float*)d_in[3];
    const float* Wm2 = (const float*)d_in[4];
    const float* bm2 = (const float*)d_in[5];
    const float* Wp1 = (const float*)d_in[6];
    const float* bp1 = (const float*)d_in[7];
    const float* Wp2 = (const float*)d_in[8];
    const float* bp2 = (const float*)d_in[9];
    const float* temp = (const float*)d_in[10];
    float* out = (float*)d_out;

    const int D     = in_sizes[3];          // 1024
    const int MOLD  = in_sizes[2] / D;      // 768
    const int PROTD = in_sizes[6] / D;      // 1280
    const int Nmol  = in_sizes[0] / MOLD;   // 4096
    const int Mprot = in_sizes[1] / PROTD;  // 8192

    __half *molA, *Wm1B, *Wm2B, *protA, *Wp1B, *Wp2B, *HmA, *HpA, *MPnB, *PPnA;
    float *MP32, *PP32;
    cudaGetSymbolAddress((void**)&molA,  g_molA);
    cudaGetSymbolAddress((void**)&Wm1B,  g_Wm1B);
    cudaGetSymbolAddress((void**)&Wm2B,  g_Wm2B);
    cudaGetSymbolAddress((void**)&protA, g_protA);
    cudaGetSymbolAddress((void**)&Wp1B,  g_Wp1B);
    cudaGetSymbolAddress((void**)&Wp2B,  g_Wp2B);
    cudaGetSymbolAddress((void**)&HmA,   g_HmA);
    cudaGetSymbolAddress((void**)&HpA,   g_HpA);
    cudaGetSymbolAddress((void**)&MPnB,  g_MPnB);
    cudaGetSymbolAddress((void**)&PPnA,  g_PPnA);
    cudaGetSymbolAddress((void**)&MP32,  g_MP32);
    cudaGetSymbolAddress((void**)&PP32,  g_PP32);

    cudaFuncSetAttribute(gemm_mma<true,  true,  false, true >,
                         cudaFuncAttributeMaxDynamicSharedMemorySize, GSMEM_TOTAL);
    cudaFuncSetAttribute(gemm_mma<false, true,  false, false>,
                         cudaFuncAttributeMaxDynamicSharedMemorySize, GSMEM_TOTAL);
    cudaFuncSetAttribute(gemm_mma<false, false, true,  false>,
                         cudaFuncAttributeMaxDynamicSharedMemorySize, GSMEM_TOTAL);

    const dim3 blk256(256);
    auto cvt = [&](const float* src, __half* dst, int elems) {
        int n4 = elems / 4;
        tofp16_kernel<<<(n4 + 255) / 256, blk256>>>(src, dst, n4);
    };

    cvt(Wm1, Wm1B, D * MOLD);
    cvt(Wm2, Wm2B, D * D);
    cvt(Wp1, Wp1B, D * PROTD);
    cvt(Wp2, Wp2B, D * D);
    cvt(molecule, molA, Nmol * MOLD);

    // --- molecule branch ---
    gemm_mma<true, true, false, true><<<dim3(D / 128, Nmol / 256), blk256, GSMEM_TOTAL>>>(
        molA, Wm1B, bm1, nullptr, HmA, Nmol, D, MOLD);
    cvt(protein, protA, Mprot * PROTD);
    gemm_mma<false, true, false, false><<<dim3(D / 128, Nmol / 256), blk256, GSMEM_TOTAL>>>(
        HmA, Wm2B, bm2, nullptr, MP32, Nmol, D, D);
    normhalf_kernel<<<Nmol, blk256>>>(MP32, MPnB, D);

    // --- protein branch ---
    gemm_mma<true, true, false, true><<<dim3(D / 128, Mprot / 256), blk256, GSMEM_TOTAL>>>(
        protA, Wp1B, bp1, nullptr, HpA, Mprot, D, PROTD);
    gemm_mma<false, true, false, false><<<dim3(D / 128, Mprot / 256), blk256, GSMEM_TOTAL>>>(
        HpA, Wp2B, bp2, nullptr, PP32, Mprot, D, D);
    normhalf_kernel<<<Mprot, blk256>>>(PP32, PPnA, D);

    // --- similarity: out[M, N] = PPn @ MPn^T / temperature ---
    gemm_mma<false, false, true, false><<<dim3(Nmol / 128, Mprot / 256), blk256, GSMEM_TOTAL>>>(
        PPnA, MPnB, nullptr, temp, out, Mprot, Nmol, D);
}

// round 14
// speedup vs baseline: 1.1598x; 1.1598x over previous
#include <cuda_runtime.h>
#include <cuda_fp16.h>
#include <cstdint>

// ----------------------------------------------------------------------------
// Coembedding via warp-level plain-fp16 mma.sync (fp32 accumulate).
// R12/R13 post-mortem: geometry-insensitive at ~295 TF/s -> either legacy-HMMA
// pipe saturation or 1-CTA/SM barrier drain. This round tests the drain
// hypothesis: 128x128 tile (96KB smem) + __launch_bounds__(256, 2) to force
// 2 CTAs/SM so one CTA's MMA covers the other's cp_wait/__syncthreads window.
// Also: all 6 fp32->fp16 converts fused into ONE multi-segment kernel.
// Shapes: N=4096, M=8192, MOL=768, PROT=1280, D=1024.
// ----------------------------------------------------------------------------

// ======================= PTX helpers (compute_100-safe) =====================
__device__ __forceinline__ uint32_t smem_u32(const void* p) {
    uint32_t a;
    asm("{ .reg .u64 t; cvta.to.shared.u64 t, %1; cvt.u32.u64 %0, t; }"
        : "=r"(a) : "l"(p));
    return a;
}
__device__ __forceinline__ void cp_async16(uint32_t dst, const void* src) {
    asm volatile("cp.async.cg.shared.global [%0], [%1], 16;\n" :: "r"(dst), "l"(src));
}
__device__ __forceinline__ void cp_commit() {
    asm volatile("cp.async.commit_group;\n");
}
template <int N> __device__ __forceinline__ void cp_wait() {
    asm volatile("cp.async.wait_group %0;\n" :: "n"(N));
}
__device__ __forceinline__ void ldsm_x4(uint32_t& r0, uint32_t& r1,
                                        uint32_t& r2, uint32_t& r3, uint32_t addr) {
    asm volatile("ldmatrix.sync.aligned.m8n8.x4.shared.b16 {%0,%1,%2,%3}, [%4];"
                 : "=r"(r0), "=r"(r1), "=r"(r2), "=r"(r3) : "r"(addr));
}
__device__ __forceinline__ void mma_fp16(float* c, const uint32_t* a, const uint32_t* b) {
    asm volatile(
        "mma.sync.aligned.m16n8k16.row.col.f32.f16.f16.f32 "
        "{%0,%1,%2,%3}, {%4,%5,%6,%7}, {%8,%9}, {%0,%1,%2,%3};"
        : "+f"(c[0]), "+f"(c[1]), "+f"(c[2]), "+f"(c[3])
        : "r"(a[0]), "r"(a[1]), "r"(a[2]), "r"(a[3]), "r"(b[0]), "r"(b[1]));
}

// ======================= scratch (allocation-free rule) =====================
__device__ __half g_molA [4096u * 768u];
__device__ __half g_Wm1B [1024u * 768u];
__device__ __half g_Wm2B [1024u * 1024u];
__device__ __half g_protA[8192u * 1280u];
__device__ __half g_Wp1B [1024u * 1280u];
__device__ __half g_Wp2B [1024u * 1024u];
__device__ __half g_HmA  [4096u * 1024u];
__device__ __half g_HpA  [8192u * 1024u];
__device__ __half g_MPnB [4096u * 1024u];
__device__ __half g_PPnA [8192u * 1024u];
__device__ float g_MP32[4096u * 1024u];
__device__ float g_PP32[8192u * 1024u];

// ======================= conversion kernels =================================
// One launch converts all 6 fp32 tensors to fp16 (segmented flat index, float4).
__global__ __launch_bounds__(256) void tofp16_multi(
    const float* __restrict__ s0, __half* __restrict__ d0, int n0,
    const float* __restrict__ s1, __half* __restrict__ d1, int n1,
    const float* __restrict__ s2, __half* __restrict__ d2, int n2,
    const float* __restrict__ s3, __half* __restrict__ d3, int n3,
    const float* __restrict__ s4, __half* __restrict__ d4, int n4c,
    const float* __restrict__ s5, __half* __restrict__ d5, int n5)
{
    int i = blockIdx.x * 256 + threadIdx.x;
    const float* s; __half* d;
    if      (i < n0)                      { s = s0; d = d0; }
    else if ((i -= n0) < n1)              { s = s1; d = d1; }
    else if ((i -= n1) < n2)              { s = s2; d = d2; }
    else if ((i -= n2) < n3)              { s = s3; d = d3; }
    else if ((i -= n3) < n4c)             { s = s4; d = d4; }
    else if ((i -= n4c) < n5)             { s = s5; d = d5; }
    else return;
    float4 v = ((const float4*)s)[i];
    ((__half2*)d)[2 * i]     = __floats2half2_rn(v.x, v.y);
    ((__half2*)d)[2 * i + 1] = __floats2half2_rn(v.z, v.w);
}

// fp32 [R,D] -> L2-normalize row (eps clamp) -> fp16 [R,D].
__global__ __launch_bounds__(256) void normhalf_kernel(
    const float* __restrict__ X, __half* __restrict__ Y, int D)
{
    const float* x = X + (size_t)blockIdx.x * D;
    __half* y = Y + (size_t)blockIdx.x * D;
    const int tid = threadIdx.x;

    float s = 0.0f;
    for (int i = tid * 4; i < D; i += 1024) {
        float4 v = *(const float4*)(x + i);
        s = fmaf(v.x, v.x, s); s = fmaf(v.y, v.y, s);
        s = fmaf(v.z, v.z, s); s = fmaf(v.w, v.w, s);
    }
    #pragma unroll
    for (int o = 16; o > 0; o >>= 1) s += __shfl_xor_sync(0xffffffff, s, o);
    __shared__ float red[8]; __shared__ float s_inv;
    if ((tid & 31) == 0) red[tid >> 5] = s;
    __syncthreads();
    if (tid == 0) {
        float t = 0.0f;
        #pragma unroll
        for (int w = 0; w < 8; w++) t += red[w];
        s_inv = 1.0f / fmaxf(sqrtf(t), 1e-8f);
    }
    __syncthreads();
    const float inv = s_inv;
    for (int i = tid * 4; i < D; i += 1024) {
        float4 v = *(const float4*)(x + i);
        *(__half2*)(y + i)     = __floats2half2_rn(v.x * inv, v.y * inv);
        *(__half2*)(y + i + 2) = __floats2half2_rn(v.z * inv, v.w * inv);
    }
}

// ======================= mma.sync fp16 GEMM =================================
// C[M,N] = A[M,K] @ B[N,K]^T (fp16, K-major), fp32 accumulate + epilogue.
// CTA tile 128x128, K-chunk 64 fp16 (128 B rows, SW128), 3 stages,
// 256 threads / 8 warps in a 4(M) x 2(N) grid; warp tile 32x64.
// __launch_bounds__(256, 2): cap 128 regs -> 2 CTAs/SM guaranteed (96KB x 2
// smem fits the 227KB carveout), so MMA covers the other CTA's barrier window.
#define TILE_B   16384                 // one operand tile: 128 rows x 128 B
#define STAGE_B  (2 * TILE_B)          // A + B
#define GSMEM_TOTAL (3 * STAGE_B)      // 98304 B dynamic smem

template <bool RELU, bool HAS_BIAS, bool HAS_SCALE, bool HALF_OUT>
__global__ __launch_bounds__(256, 2) void gemm_mma(
    const __half* __restrict__ A, const __half* __restrict__ B,
    const float* __restrict__ bias, const float* __restrict__ tempPtr,
    void* __restrict__ Cv, int M, int N, int K)
{
    extern __shared__ char smem[];
    const uint32_t sbase = smem_u32(smem);
    const int tid = threadIdx.x;
    const int lane = tid & 31;
    const int wid = tid >> 5;
    const int warpM = wid & 3;          // 4 warps along M (32 rows each)
    const int warpN = wid >> 2;         // 2 warps along N (64 cols each)

    const int rowBase = blockIdx.y * 128;
    const int colBase = blockIdx.x * 128;
    const size_t stride = (size_t)K * 2;            // bytes per row (A and B)
    const char* Ab = (const char*)A + (size_t)rowBase * stride;
    const char* Bb = (const char*)B + (size_t)colBase * stride;
    const int T = K / 64;                           // K-chunks

    // ---- cp.async tile loader: 4 x (A16B + B16B) per thread, 1 group/tile.
    auto load_tile = [&](int t, int s) {
        const uint32_t sA = sbase + s * STAGE_B;
        const uint32_t sB = sA + TILE_B;
        const size_t kb = (size_t)t * 128;
        #pragma unroll
        for (int i = 0; i < 4; i++) {
            int id = tid + i * 256;
            int row = id >> 3;
            int c = (id & 7) << 4;
            uint32_t doff = row * 128 + (c ^ ((row & 7) << 4));
            cp_async16(sA + doff, Ab + (size_t)row * stride + kb + c);
            cp_async16(sB + doff, Bb + (size_t)row * stride + kb + c);
        }
        cp_commit();
    };

    // ---- ldmatrix lane-address components (canonical m16n8k16 layouts).
    const int aRowL = lane & 15;
    const uint32_t aHalf = (uint32_t)((lane >> 4) << 4);   // 0 or 16 bytes
    uint32_t aRowOff[2], aXor[2];
    #pragma unroll
    for (int mi = 0; mi < 2; mi++) {
        int r = warpM * 32 + mi * 16 + aRowL;
        aRowOff[mi] = r * 128;
        aXor[mi] = (r & 7) << 4;
    }
    const int bRowL = (lane & 7) + ((lane >> 4) << 3);
    const uint32_t bHalf = (uint32_t)(((lane >> 3) & 1) << 4);
    uint32_t bRowOff[4], bXor[4];
    #pragma unroll
    for (int p = 0; p < 4; p++) {
        int r = warpN * 64 + p * 16 + bRowL;
        bRowOff[p] = r * 128;
        bXor[p] = (r & 7) << 4;
    }

    float acc[2][8][4];
    #pragma unroll
    for (int mi = 0; mi < 2; mi++)
        #pragma unroll
        for (int ni = 0; ni < 8; ni++)
            #pragma unroll
            for (int u = 0; u < 4; u++) acc[mi][ni][u] = 0.0f;

    // ---- prologue: stages 0,1.
    load_tile(0, 0);
    load_tile(1, 1);

    for (int t = 0; t < T; t++) {
        cp_wait<1>();            // tile t's group complete
        __syncthreads();         // everyone done reading stage (t+2)%3
        if (t + 2 < T) load_tile(t + 2, (t + 2) % 3);
        else           cp_commit();   // keep group ledger uniform in the tail

        const uint32_t sA = sbase + (t % 3) * STAGE_B;
        const uint32_t sB = sA + TILE_B;

        #pragma unroll
        for (int ks = 0; ks < 4; ks++) {           // 4 x k16 per 64-elem chunk
            const uint32_t kA = ks * 32 + aHalf;   // byte col in 128B row
            const uint32_t kB = ks * 32 + bHalf;
            uint32_t a[2][4];
            uint32_t b[8][2];
            #pragma unroll
            for (int mi = 0; mi < 2; mi++)
                ldsm_x4(a[mi][0], a[mi][1], a[mi][2], a[mi][3],
                        sA + aRowOff[mi] + (kA ^ aXor[mi]));
            #pragma unroll
            for (int p = 0; p < 4; p++) {
                uint32_t r0, r1, r2, r3;
                ldsm_x4(r0, r1, r2, r3, sB + bRowOff[p] + (kB ^ bXor[p]));
                b[2 * p][0] = r0; b[2 * p][1] = r1;
                b[2 * p + 1][0] = r2; b[2 * p + 1][1] = r3;
            }
            #pragma unroll
            for (int mi = 0; mi < 2; mi++)
                #pragma unroll
                for (int ni = 0; ni < 8; ni++)
                    mma_fp16(acc[mi][ni], a[mi], b[ni]);
        }
    }

    // ---- epilogue: bias / ReLU / scale; fp32 or fp16 stores.
    float alpha = 1.0f;
    if (HAS_SCALE) alpha = 1.0f / (*tempPtr);
    const int orow0 = rowBase + warpM * 32;
    const int ocol0 = colBase + warpN * 64;
    const int qr = lane >> 2;
    const int qc = (lane & 3) << 1;

    #pragma unroll
    for (int mi = 0; mi < 2; mi++) {
        const int r0 = orow0 + mi * 16 + qr;
        #pragma unroll
        for (int ni = 0; ni < 8; ni++) {
            const int cc = ocol0 + ni * 8 + qc;
            float b0 = 0.0f, b1 = 0.0f;
            if (HAS_BIAS) { b0 = bias[cc]; b1 = bias[cc + 1]; }
            float v0 = acc[mi][ni][0] + b0;
            float v1 = acc[mi][ni][1] + b1;
            float v2 = acc[mi][ni][2] + b0;
            float v3 = acc[mi][ni][3] + b1;
            if (RELU) {
                v0 = fmaxf(v0, 0.0f); v1 = fmaxf(v1, 0.0f);
                v2 = fmaxf(v2, 0.0f); v3 = fmaxf(v3, 0.0f);
            }
            if (HAS_SCALE) { v0 *= alpha; v1 *= alpha; v2 *= alpha; v3 *= alpha; }
            if (HALF_OUT) {
                __half* Ch = (__half*)Cv;
                *(__half2*)(Ch + (size_t)r0 * N + cc)       = __floats2half2_rn(v0, v1);
                *(__half2*)(Ch + (size_t)(r0 + 8) * N + cc) = __floats2half2_rn(v2, v3);
            } else {
                float* C = (float*)Cv;
                float2 o0 = {v0, v1}, o1 = {v2, v3};
                *(float2*)(C + (size_t)r0 * N + cc) = o0;
                *(float2*)(C + (size_t)(r0 + 8) * N + cc) = o1;
            }
        }
    }
}

// ======================= host wiring ========================================
extern "C" void kernel_launch(void* const* d_in, const int* in_sizes, int n_in,
                              void* d_out, int out_size)
{
    const float* molecule = (const float*)d_in[0];
    const float* protein  = (const float*)d_in[1];
    const float* Wm1 = (const float*)d_in[2];
    const float* bm1 = (const float*)d_in[3];
    const float* Wm2 = (const float*)d_in[4];
    const float* bm2 = (const float*)d_in[5];
    const float* Wp1 = (const float*)d_in[6];
    const float* bp1 = (const float*)d_in[7];
    const float* Wp2 = (const float*)d_in[8];
    const float* bp2 = (const float*)d_in[9];
    const float* temp = (const float*)d_in[10];
    float* out = (float*)d_out;

    const int D     = in_sizes[3];          // 1024
    const int MOLD  = in_sizes[2] / D;      // 768
    const int PROTD = in_sizes[6] / D;      // 1280
    const int Nmol  = in_sizes[0] / MOLD;   // 4096
    const int Mprot = in_sizes[1] / PROTD;  // 8192

    __half *molA, *Wm1B, *Wm2B, *protA, *Wp1B, *Wp2B, *HmA, *HpA, *MPnB, *PPnA;
    float *MP32, *PP32;
    cudaGetSymbolAddress((void**)&molA,  g_molA);
    cudaGetSymbolAddress((void**)&Wm1B,  g_Wm1B);
    cudaGetSymbolAddress((void**)&Wm2B,  g_Wm2B);
    cudaGetSymbolAddress((void**)&protA, g_protA);
    cudaGetSymbolAddress((void**)&Wp1B,  g_Wp1B);
    cudaGetSymbolAddress((void**)&Wp2B,  g_Wp2B);
    cudaGetSymbolAddress((void**)&HmA,   g_HmA);
    cudaGetSymbolAddress((void**)&HpA,   g_HpA);
    cudaGetSymbolAddress((void**)&MPnB,  g_MPnB);
    cudaGetSymbolAddress((void**)&PPnA,  g_PPnA);
    cudaGetSymbolAddress((void**)&MP32,  g_MP32);
    cudaGetSymbolAddress((void**)&PP32,  g_PP32);

    cudaFuncSetAttribute(gemm_mma<true,  true,  false, true >,
                         cudaFuncAttributeMaxDynamicSharedMemorySize, GSMEM_TOTAL);
    cudaFuncSetAttribute(gemm_mma<false, true,  false, false>,
                         cudaFuncAttributeMaxDynamicSharedMemorySize, GSMEM_TOTAL);
    cudaFuncSetAttribute(gemm_mma<false, false, true,  false>,
                         cudaFuncAttributeMaxDynamicSharedMemorySize, GSMEM_TOTAL);

    const dim3 blk256(256);

    // Launch 0: ONE fused convert for all six fp32->fp16 tensors.
    const int c0 = D * MOLD / 4;            // Wm1
    const int c1 = D * D / 4;               // Wm2
    const int c2 = D * PROTD / 4;           // Wp1
    const int c3 = D * D / 4;               // Wp2
    const int c4 = Nmol * MOLD / 4;         // molecule
    const int c5 = Mprot * PROTD / 4;       // protein
    const int ctot = c0 + c1 + c2 + c3 + c4 + c5;
    tofp16_multi<<<(ctot + 255) / 256, blk256>>>(
        Wm1, Wm1B, c0, Wm2, Wm2B, c1, Wp1, Wp1B, c2,
        Wp2, Wp2B, c3, molecule, molA, c4, protein, protA, c5);

    // --- molecule branch ---
    gemm_mma<true, true, false, true><<<dim3(D / 128, Nmol / 128), blk256, GSMEM_TOTAL>>>(
        molA, Wm1B, bm1, nullptr, HmA, Nmol, D, MOLD);                        // 1
    gemm_mma<false, true, false, false><<<dim3(D / 128, Nmol / 128), blk256, GSMEM_TOTAL>>>(
        HmA, Wm2B, bm2, nullptr, MP32, Nmol, D, D);                           // 2
    normhalf_kernel<<<Nmol, blk256>>>(MP32, MPnB, D);                         // 3

    // --- protein branch ---
    gemm_mma<true, true, false, true><<<dim3(D / 128, Mprot / 128), blk256, GSMEM_TOTAL>>>(
        protA, Wp1B, bp1, nullptr, HpA, Mprot, D, PROTD);                     // 4
    gemm_mma<false, true, false, false><<<dim3(D / 128, Mprot / 128), blk256, GSMEM_TOTAL>>>(
        HpA, Wp2B, bp2, nullptr, PP32, Mprot, D, D);                          // 5
    normhalf_kernel<<<Mprot, blk256>>>(PP32, PPnA, D);                        // 6

    // --- similarity: out[M, N] = PPn @ MPn^T / temperature ---
    gemm_mma<false, false, true, false><<<dim3(Nmol / 128, Mprot / 128), blk256, GSMEM_TOTAL>>>(
        PPnA, MPnB, nullptr, temp, out, Mprot, Nmol, D);                      // 7
}

// round 15
// speedup vs baseline: 1.1954x; 1.0307x over previous
#include <cuda_runtime.h>
#include <cuda_fp16.h>
#include <cstdint>

// ----------------------------------------------------------------------------
// Coembedding via warp-level plain-fp16 mma.sync (fp32 accumulate).
// R14: 412us (2 CTAs/SM confirmed worth ~50us). This round fuses the
// normalization algebraically: normalize-then-GEMM == GEMM-then-scale, so
//  - layer-2 GEMMs write fp16 UNNORMALIZED projections (no fp32 round-trip),
//  - a warp-per-row kernel computes invNorm[i] = 1/max(||row||,eps),
//  - the similarity epilogue multiplies by invP[row]*invM[col]/temp.
// One fp16 rounding on the projections either way -> precision unchanged.
// GEMM core identical to the validated R14 core (128x128x64, 8 warps,
// 3-stage cp.async, SW128, __launch_bounds__(256,2) for 2 CTAs/SM).
// Shapes: N=4096, M=8192, MOL=768, PROT=1280, D=1024.
// ----------------------------------------------------------------------------

// ======================= PTX helpers (compute_100-safe) =====================
__device__ __forceinline__ uint32_t smem_u32(const void* p) {
    uint32_t a;
    asm("{ .reg .u64 t; cvta.to.shared.u64 t, %1; cvt.u32.u64 %0, t; }"
        : "=r"(a) : "l"(p));
    return a;
}
__device__ __forceinline__ void cp_async16(uint32_t dst, const void* src) {
    asm volatile("cp.async.cg.shared.global [%0], [%1], 16;\n" :: "r"(dst), "l"(src));
}
__device__ __forceinline__ void cp_commit() {
    asm volatile("cp.async.commit_group;\n");
}
template <int N> __device__ __forceinline__ void cp_wait() {
    asm volatile("cp.async.wait_group %0;\n" :: "n"(N));
}
__device__ __forceinline__ void ldsm_x4(uint32_t& r0, uint32_t& r1,
                                        uint32_t& r2, uint32_t& r3, uint32_t addr) {
    asm volatile("ldmatrix.sync.aligned.m8n8.x4.shared.b16 {%0,%1,%2,%3}, [%4];"
                 : "=r"(r0), "=r"(r1), "=r"(r2), "=r"(r3) : "r"(addr));
}
__device__ __forceinline__ void mma_fp16(float* c, const uint32_t* a, const uint32_t* b) {
    asm volatile(
        "mma.sync.aligned.m16n8k16.row.col.f32.f16.f16.f32 "
        "{%0,%1,%2,%3}, {%4,%5,%6,%7}, {%8,%9}, {%0,%1,%2,%3};"
        : "+f"(c[0]), "+f"(c[1]), "+f"(c[2]), "+f"(c[3])
        : "r"(a[0]), "r"(a[1]), "r"(a[2]), "r"(a[3]), "r"(b[0]), "r"(b[1]));
}

// ======================= scratch (allocation-free rule) =====================
__device__ __half g_molA [4096u * 768u];
__device__ __half g_Wm1B [1024u * 768u];
__device__ __half g_Wm2B [1024u * 1024u];
__device__ __half g_protA[8192u * 1280u];
__device__ __half g_Wp1B [1024u * 1280u];
__device__ __half g_Wp2B [1024u * 1024u];
__device__ __half g_HmA  [4096u * 1024u];
__device__ __half g_HpA  [8192u * 1024u];
__device__ __half g_MPu  [4096u * 1024u];   // unnormalized mol projection (fp16)
__device__ __half g_PPu  [8192u * 1024u];   // unnormalized prot projection (fp16)
__device__ float g_invM[4096u];
__device__ float g_invP[8192u];

// ======================= conversion kernels =================================
// One launch converts all 6 fp32 tensors to fp16 (segmented flat index, float4).
__global__ __launch_bounds__(256) void tofp16_multi(
    const float* __restrict__ s0, __half* __restrict__ d0, int n0,
    const float* __restrict__ s1, __half* __restrict__ d1, int n1,
    const float* __restrict__ s2, __half* __restrict__ d2, int n2,
    const float* __restrict__ s3, __half* __restrict__ d3, int n3,
    const float* __restrict__ s4, __half* __restrict__ d4, int n4c,
    const float* __restrict__ s5, __half* __restrict__ d5, int n5)
{
    int i = blockIdx.x * 256 + threadIdx.x;
    const float* s; __half* d;
    if      (i < n0)                      { s = s0; d = d0; }
    else if ((i -= n0) < n1)              { s = s1; d = d1; }
    else if ((i -= n1) < n2)              { s = s2; d = d2; }
    else if ((i -= n2) < n3)              { s = s3; d = d3; }
    else if ((i -= n3) < n4c)             { s = s4; d = d4; }
    else if ((i -= n4c) < n5)             { s = s5; d = d5; }
    else return;
    float4 v = ((const float4*)s)[i];
    ((__half2*)d)[2 * i]     = __floats2half2_rn(v.x, v.y);
    ((__half2*)d)[2 * i + 1] = __floats2half2_rn(v.z, v.w);
}

// fp16 [R,D] -> inv[r] = 1 / max(||row r||, 1e-8). One warp per row.
__global__ __launch_bounds__(256) void rowinv_kernel(
    const __half* __restrict__ X, float* __restrict__ inv, int D)
{
    const int row = blockIdx.x * 8 + (threadIdx.x >> 5);
    const int lane = threadIdx.x & 31;
    const __half2* x = (const __half2*)(X + (size_t)row * D);
    float s = 0.0f;
    for (int i = lane; i < D / 2; i += 32) {
        float2 v = __half22float2(x[i]);
        s = fmaf(v.x, v.x, s);
        s = fmaf(v.y, v.y, s);
    }
    #pragma unroll
    for (int o = 16; o > 0; o >>= 1) s += __shfl_xor_sync(0xffffffff, s, o);
    if (lane == 0) inv[row] = 1.0f / fmaxf(sqrtf(s), 1e-8f);
}

// ======================= mma.sync fp16 GEMM =================================
// C[M,N] = A[M,K] @ B[N,K]^T (fp16, K-major), fp32 accumulate + epilogue.
// CTA tile 128x128, K-chunk 64 fp16 (128 B rows, SW128), 3 stages,
// 256 threads / 8 warps, warp tile 32x64; __launch_bounds__(256,2) -> 2 CTA/SM.
// SCALE_NORM: out *= invRow[row] * invCol[col] / (*tempPtr)  (similarity GEMM).
#define TILE_B   16384                 // one operand tile: 128 rows x 128 B
#define STAGE_B  (2 * TILE_B)          // A + B
#define GSMEM_TOTAL (3 * STAGE_B)      // 98304 B dynamic smem

template <bool RELU, bool HAS_BIAS, bool SCALE_NORM, bool HALF_OUT>
__global__ __launch_bounds__(256, 2) void gemm_mma(
    const __half* __restrict__ A, const __half* __restrict__ B,
    const float* __restrict__ bias, const float* __restrict__ tempPtr,
    const float* __restrict__ invRow, const float* __restrict__ invCol,
    void* __restrict__ Cv, int M, int N, int K)
{
    extern __shared__ char smem[];
    const uint32_t sbase = smem_u32(smem);
    const int tid = threadIdx.x;
    const int lane = tid & 31;
    const int wid = tid >> 5;
    const int warpM = wid & 3;          // 4 warps along M (32 rows each)
    const int warpN = wid >> 2;         // 2 warps along N (64 cols each)

    const int rowBase = blockIdx.y * 128;
    const int colBase = blockIdx.x * 128;
    const size_t stride = (size_t)K * 2;            // bytes per row (A and B)
    const char* Ab = (const char*)A + (size_t)rowBase * stride;
    const char* Bb = (const char*)B + (size_t)colBase * stride;
    const int T = K / 64;                           // K-chunks

    auto load_tile = [&](int t, int s) {
        const uint32_t sA = sbase + s * STAGE_B;
        const uint32_t sB = sA + TILE_B;
        const size_t kb = (size_t)t * 128;
        #pragma unroll
        for (int i = 0; i < 4; i++) {
            int id = tid + i * 256;
            int row = id >> 3;
            int c = (id & 7) << 4;
            uint32_t doff = row * 128 + (c ^ ((row & 7) << 4));
            cp_async16(sA + doff, Ab + (size_t)row * stride + kb + c);
            cp_async16(sB + doff, Bb + (size_t)row * stride + kb + c);
        }
        cp_commit();
    };

    const int aRowL = lane & 15;
    const uint32_t aHalf = (uint32_t)((lane >> 4) << 4);   // 0 or 16 bytes
    uint32_t aRowOff[2], aXor[2];
    #pragma unroll
    for (int mi = 0; mi < 2; mi++) {
        int r = warpM * 32 + mi * 16 + aRowL;
        aRowOff[mi] = r * 128;
        aXor[mi] = (r & 7) << 4;
    }
    const int bRowL = (lane & 7) + ((lane >> 4) << 3);
    const uint32_t bHalf = (uint32_t)(((lane >> 3) & 1) << 4);
    uint32_t bRowOff[4], bXor[4];
    #pragma unroll
    for (int p = 0; p < 4; p++) {
        int r = warpN * 64 + p * 16 + bRowL;
        bRowOff[p] = r * 128;
        bXor[p] = (r & 7) << 4;
    }

    float acc[2][8][4];
    #pragma unroll
    for (int mi = 0; mi < 2; mi++)
        #pragma unroll
        for (int ni = 0; ni < 8; ni++)
            #pragma unroll
            for (int u = 0; u < 4; u++) acc[mi][ni][u] = 0.0f;

    load_tile(0, 0);
    load_tile(1, 1);

    for (int t = 0; t < T; t++) {
        cp_wait<1>();            // tile t's group complete
        __syncthreads();         // everyone done reading stage (t+2)%3
        if (t + 2 < T) load_tile(t + 2, (t + 2) % 3);
        else           cp_commit();   // keep group ledger uniform in the tail

        const uint32_t sA = sbase + (t % 3) * STAGE_B;
        const uint32_t sB = sA + TILE_B;

        #pragma unroll
        for (int ks = 0; ks < 4; ks++) {           // 4 x k16 per 64-elem chunk
            const uint32_t kA = ks * 32 + aHalf;
            const uint32_t kB = ks * 32 + bHalf;
            uint32_t a[2][4];
            uint32_t b[8][2];
            #pragma unroll
            for (int mi = 0; mi < 2; mi++)
                ldsm_x4(a[mi][0], a[mi][1], a[mi][2], a[mi][3],
                        sA + aRowOff[mi] + (kA ^ aXor[mi]));
            #pragma unroll
            for (int p = 0; p < 4; p++) {
                uint32_t r0, r1, r2, r3;
                ldsm_x4(r0, r1, r2, r3, sB + bRowOff[p] + (kB ^ bXor[p]));
                b[2 * p][0] = r0; b[2 * p][1] = r1;
                b[2 * p + 1][0] = r2; b[2 * p + 1][1] = r3;
            }
            #pragma unroll
            for (int mi = 0; mi < 2; mi++)
                #pragma unroll
                for (int ni = 0; ni < 8; ni++)
                    mma_fp16(acc[mi][ni], a[mi], b[ni]);
        }
    }

    // ---- epilogue.
    float alpha = 1.0f;
    if (SCALE_NORM) alpha = 1.0f / (*tempPtr);
    const int orow0 = rowBase + warpM * 32;
    const int ocol0 = colBase + warpN * 64;
    const int qr = lane >> 2;
    const int qc = (lane & 3) << 1;

    #pragma unroll
    for (int mi = 0; mi < 2; mi++) {
        const int r0 = orow0 + mi * 16 + qr;
        float ri0 = 1.0f, ri1 = 1.0f;
        if (SCALE_NORM) {
            ri0 = invRow[r0] * alpha;
            ri1 = invRow[r0 + 8] * alpha;
        }
        #pragma unroll
        for (int ni = 0; ni < 8; ni++) {
            const int cc = ocol0 + ni * 8 + qc;
            float b0 = 0.0f, b1 = 0.0f;
            if (HAS_BIAS) { b0 = bias[cc]; b1 = bias[cc + 1]; }
            float v0 = acc[mi][ni][0] + b0;
            float v1 = acc[mi][ni][1] + b1;
            float v2 = acc[mi][ni][2] + b0;
            float v3 = acc[mi][ni][3] + b1;
            if (RELU) {
                v0 = fmaxf(v0, 0.0f); v1 = fmaxf(v1, 0.0f);
                v2 = fmaxf(v2, 0.0f); v3 = fmaxf(v3, 0.0f);
            }
            if (SCALE_NORM) {
                const float ci0 = invCol[cc];
                const float ci1 = invCol[cc + 1];
                v0 *= ri0 * ci0; v1 *= ri0 * ci1;
                v2 *= ri1 * ci0; v3 *= ri1 * ci1;
            }
            if (HALF_OUT) {
                __half* Ch = (__half*)Cv;
                *(__half2*)(Ch + (size_t)r0 * N + cc)       = __floats2half2_rn(v0, v1);
                *(__half2*)(Ch + (size_t)(r0 + 8) * N + cc) = __floats2half2_rn(v2, v3);
            } else {
                float* C = (float*)Cv;
                float2 o0 = {v0, v1}, o1 = {v2, v3};
                *(float2*)(C + (size_t)r0 * N + cc) = o0;
                *(float2*)(C + (size_t)(r0 + 8) * N + cc) = o1;
            }
        }
    }
}

// ======================= host wiring ========================================
extern "C" void kernel_launch(void* const* d_in, const int* in_sizes, int n_in,
                              void* d_out, int out_size)
{
    const float* molecule = (const float*)d_in[0];
    const float* protein  = (const float*)d_in[1];
    const float* Wm1 = (const float*)d_in[2];
    const float* bm1 = (const float*)d_in[3];
    const float* Wm2 = (const float*)d_in[4];
    const float* bm2 = (const float*)d_in[5];
    const float* Wp1 = (const float*)d_in[6];
    const float* bp1 = (const float*)d_in[7];
    const float* Wp2 = (const float*)d_in[8];
    const float* bp2 = (const float*)d_in[9];
    const float* temp = (const float*)d_in[10];
    float* out = (float*)d_out;

    const int D     = in_sizes[3];          // 1024
    const int MOLD  = in_sizes[2] / D;      // 768
    const int PROTD = in_sizes[6] / D;      // 1280
    const int Nmol  = in_sizes[0] / MOLD;   // 4096
    const int Mprot = in_sizes[1] / PROTD;  // 8192

    __half *molA, *Wm1B, *Wm2B, *protA, *Wp1B, *Wp2B, *HmA, *HpA, *MPu, *PPu;
    float *invM, *invP;
    cudaGetSymbolAddress((void**)&molA,  g_molA);
    cudaGetSymbolAddress((void**)&Wm1B,  g_Wm1B);
    cudaGetSymbolAddress((void**)&Wm2B,  g_Wm2B);
    cudaGetSymbolAddress((void**)&protA, g_protA);
    cudaGetSymbolAddress((void**)&Wp1B,  g_Wp1B);
    cudaGetSymbolAddress((void**)&Wp2B,  g_Wp2B);
    cudaGetSymbolAddress((void**)&HmA,   g_HmA);
    cudaGetSymbolAddress((void**)&HpA,   g_HpA);
    cudaGetSymbolAddress((void**)&MPu,   g_MPu);
    cudaGetSymbolAddress((void**)&PPu,   g_PPu);
    cudaGetSymbolAddress((void**)&invM,  g_invM);
    cudaGetSymbolAddress((void**)&invP,  g_invP);

    cudaFuncSetAttribute(gemm_mma<true,  true,  false, true >,
                         cudaFuncAttributeMaxDynamicSharedMemorySize, GSMEM_TOTAL);
    cudaFuncSetAttribute(gemm_mma<false, true,  false, true >,
                         cudaFuncAttributeMaxDynamicSharedMemorySize, GSMEM_TOTAL);
    cudaFuncSetAttribute(gemm_mma<false, false, true,  false>,
                         cudaFuncAttributeMaxDynamicSharedMemorySize, GSMEM_TOTAL);

    const dim3 blk256(256);

    // Launch 0: ONE fused convert for all six fp32->fp16 tensors.
    const int c0 = D * MOLD / 4;
    const int c1 = D * D / 4;
    const int c2 = D * PROTD / 4;
    const int c3 = D * D / 4;
    const int c4 = Nmol * MOLD / 4;
    const int c5 = Mprot * PROTD / 4;
    const int ctot = c0 + c1 + c2 + c3 + c4 + c5;
    tofp16_multi<<<(ctot + 255) / 256, blk256>>>(
        Wm1, Wm1B, c0, Wm2, Wm2B, c1, Wp1, Wp1B, c2,
        Wp2, Wp2B, c3, molecule, molA, c4, protein, protA, c5);

    // --- molecule branch ---
    gemm_mma<true, true, false, true><<<dim3(D / 128, Nmol / 128), blk256, GSMEM_TOTAL>>>(
        molA, Wm1B, bm1, nullptr, nullptr, nullptr, HmA, Nmol, D, MOLD);
    gemm_mma<false, true, false, true><<<dim3(D / 128, Nmol / 128), blk256, GSMEM_TOTAL>>>(
        HmA, Wm2B, bm2, nullptr, nullptr, nullptr, MPu, Nmol, D, D);
    rowinv_kernel<<<Nmol / 8, blk256>>>(MPu, invM, D);

    // --- protein branch ---
    gemm_mma<true, true, false, true><<<dim3(D / 128, Mprot / 128), blk256, GSMEM_TOTAL>>>(
        protA, Wp1B, bp1, nullptr, nullptr, nullptr, HpA, Mprot, D, PROTD);
    gemm_mma<false, true, false, true><<<dim3(D / 128, Mprot / 128), blk256, GSMEM_TOTAL>>>(
        HpA, Wp2B, bp2, nullptr, nullptr, nullptr, PPu, Mprot, D, D);
    rowinv_kernel<<<Mprot / 8, blk256>>>(PPu, invP, D);

    // --- similarity: out[i,j] = (PPu_i . MPu_j) * invP[i] * invM[j] / temp ---
    gemm_mma<false, false, true, false><<<dim3(Nmol / 128, Mprot / 128), blk256, GSMEM_TOTAL>>>(
        PPu, MPu, nullptr, temp, invP, invM, out, Mprot, Nmol, D);
}

// round 16
// speedup vs baseline: 1.2204x; 1.0209x over previous
#include <cuda_runtime.h>
#include <cuda_fp16.h>
#include <cstdint>

// ----------------------------------------------------------------------------
// Coembedding via warp-level plain-fp16 mma.sync (fp32 accumulate).
// R15: 399us. GEMM pinned at ~330 TF/s across 3 configs (legacy-HMMA pipe
// ceiling). This round improves WAVE PACKING: the mol/prot branch GEMMs are
// independent and share N=1024, so each layer's pair merges into ONE dual-
// problem launch (blockIdx.y selects problem; mol rows first). mol-L1 alone
// was 256 CTAs vs 296 resident slots -- merged grids pack far better.
// rowinv also merged. Launches: convert, L1-dual, L2-dual, rowinv-dual, sim.
// Shapes: N=4096, M=8192, MOL=768, PROT=1280, D=1024.
// ----------------------------------------------------------------------------

// ======================= PTX helpers (compute_100-safe) =====================
__device__ __forceinline__ uint32_t smem_u32(const void* p) {
    uint32_t a;
    asm("{ .reg .u64 t; cvta.to.shared.u64 t, %1; cvt.u32.u64 %0, t; }"
        : "=r"(a) : "l"(p));
    return a;
}
__device__ __forceinline__ void cp_async16(uint32_t dst, const void* src) {
    asm volatile("cp.async.cg.shared.global [%0], [%1], 16;\n" :: "r"(dst), "l"(src));
}
__device__ __forceinline__ void cp_commit() {
    asm volatile("cp.async.commit_group;\n");
}
template <int N> __device__ __forceinline__ void cp_wait() {
    asm volatile("cp.async.wait_group %0;\n" :: "n"(N));
}
__device__ __forceinline__ void ldsm_x4(uint32_t& r0, uint32_t& r1,
                                        uint32_t& r2, uint32_t& r3, uint32_t addr) {
    asm volatile("ldmatrix.sync.aligned.m8n8.x4.shared.b16 {%0,%1,%2,%3}, [%4];"
                 : "=r"(r0), "=r"(r1), "=r"(r2), "=r"(r3) : "r"(addr));
}
__device__ __forceinline__ void mma_fp16(float* c, const uint32_t* a, const uint32_t* b) {
    asm volatile(
        "mma.sync.aligned.m16n8k16.row.col.f32.f16.f16.f32 "
        "{%0,%1,%2,%3}, {%4,%5,%6,%7}, {%8,%9}, {%0,%1,%2,%3};"
        : "+f"(c[0]), "+f"(c[1]), "+f"(c[2]), "+f"(c[3])
        : "r"(a[0]), "r"(a[1]), "r"(a[2]), "r"(a[3]), "r"(b[0]), "r"(b[1]));
}

// ======================= scratch (allocation-free rule) =====================
__device__ __half g_molA [4096u * 768u];
__device__ __half g_Wm1B [1024u * 768u];
__device__ __half g_Wm2B [1024u * 1024u];
__device__ __half g_protA[8192u * 1280u];
__device__ __half g_Wp1B [1024u * 1280u];
__device__ __half g_Wp2B [1024u * 1024u];
__device__ __half g_HmA  [4096u * 1024u];
__device__ __half g_HpA  [8192u * 1024u];
__device__ __half g_MPu  [4096u * 1024u];   // unnormalized mol projection (fp16)
__device__ __half g_PPu  [8192u * 1024u];   // unnormalized prot projection (fp16)
__device__ float g_invM[4096u];
__device__ float g_invP[8192u];

// ======================= conversion kernels =================================
// One launch converts all 6 fp32 tensors to fp16 (segmented flat index, float4).
__global__ __launch_bounds__(256) void tofp16_multi(
    const float* __restrict__ s0, __half* __restrict__ d0, int n0,
    const float* __restrict__ s1, __half* __restrict__ d1, int n1,
    const float* __restrict__ s2, __half* __restrict__ d2, int n2,
    const float* __restrict__ s3, __half* __restrict__ d3, int n3,
    const float* __restrict__ s4, __half* __restrict__ d4, int n4c,
    const float* __restrict__ s5, __half* __restrict__ d5, int n5)
{
    int i = blockIdx.x * 256 + threadIdx.x;
    const float* s; __half* d;
    if      (i < n0)                      { s = s0; d = d0; }
    else if ((i -= n0) < n1)              { s = s1; d = d1; }
    else if ((i -= n1) < n2)              { s = s2; d = d2; }
    else if ((i -= n2) < n3)              { s = s3; d = d3; }
    else if ((i -= n3) < n4c)             { s = s4; d = d4; }
    else if ((i -= n4c) < n5)             { s = s5; d = d5; }
    else return;
    float4 v = ((const float4*)s)[i];
    ((__half2*)d)[2 * i]     = __floats2half2_rn(v.x, v.y);
    ((__half2*)d)[2 * i + 1] = __floats2half2_rn(v.z, v.w);
}

// Dual fp16 row-inv-norm: rows [0,R0) from X0 -> inv0, rows [R0,R0+R1) from X1.
__global__ __launch_bounds__(256) void rowinv_dual(
    const __half* __restrict__ X0, float* __restrict__ inv0, int R0,
    const __half* __restrict__ X1, float* __restrict__ inv1, int D)
{
    int row = blockIdx.x * 8 + (threadIdx.x >> 5);
    const int lane = threadIdx.x & 31;
    const __half2* x;
    float* inv;
    if (row < R0) { x = (const __half2*)(X0 + (size_t)row * D); inv = inv0 + row; }
    else { row -= R0; x = (const __half2*)(X1 + (size_t)row * D); inv = inv1 + row; }
    float s = 0.0f;
    for (int i = lane; i < D / 2; i += 32) {
        float2 v = __half22float2(x[i]);
        s = fmaf(v.x, v.x, s);
        s = fmaf(v.y, v.y, s);
    }
    #pragma unroll
    for (int o = 16; o > 0; o >>= 1) s += __shfl_xor_sync(0xffffffff, s, o);
    if (lane == 0) *inv = 1.0f / fmaxf(sqrtf(s), 1e-8f);
}

// ======================= mma.sync fp16 GEMM core ============================
#define TILE_B   16384                 // one operand tile: 128 rows x 128 B
#define STAGE_B  (2 * TILE_B)          // A + B
#define GSMEM_TOTAL (3 * STAGE_B)      // 98304 B dynamic smem

// Shared mainloop: accumulates C128x128 tile at (rowBase, colBase).
// Defined as a macro-free inline function operating on locals.
struct GemmCtx {
    const char* Ab; const char* Bb; size_t stride; int T;
    uint32_t sbase;
    uint32_t aRowOff[2], aXor[2], bRowOff[4], bXor[4];
    uint32_t aHalf, bHalf;
    int tid;
};

__device__ __forceinline__ void gemm_mainloop(GemmCtx& g, float acc[2][8][4]) {
    auto load_tile = [&](int t, int s) {
        const uint32_t sA = g.sbase + s * STAGE_B;
        const uint32_t sB = sA + TILE_B;
        const size_t kb = (size_t)t * 128;
        #pragma unroll
        for (int i = 0; i < 4; i++) {
            int id = g.tid + i * 256;
            int row = id >> 3;
            int c = (id & 7) << 4;
            uint32_t doff = row * 128 + (c ^ ((row & 7) << 4));
            cp_async16(sA + doff, g.Ab + (size_t)row * g.stride + kb + c);
            cp_async16(sB + doff, g.Bb + (size_t)row * g.stride + kb + c);
        }
        cp_commit();
    };

    load_tile(0, 0);
    load_tile(1, 1);

    for (int t = 0; t < g.T; t++) {
        cp_wait<1>();
        __syncthreads();
        if (t + 2 < g.T) load_tile(t + 2, (t + 2) % 3);
        else             cp_commit();

        const uint32_t sA = g.sbase + (t % 3) * STAGE_B;
        const uint32_t sB = sA + TILE_B;

        #pragma unroll
        for (int ks = 0; ks < 4; ks++) {
            const uint32_t kA = ks * 32 + g.aHalf;
            const uint32_t kB = ks * 32 + g.bHalf;
            uint32_t a[2][4];
            uint32_t b[8][2];
            #pragma unroll
            for (int mi = 0; mi < 2; mi++)
                ldsm_x4(a[mi][0], a[mi][1], a[mi][2], a[mi][3],
                        sA + g.aRowOff[mi] + (kA ^ g.aXor[mi]));
            #pragma unroll
            for (int p = 0; p < 4; p++) {
                uint32_t r0, r1, r2, r3;
                ldsm_x4(r0, r1, r2, r3, sB + g.bRowOff[p] + (kB ^ g.bXor[p]));
                b[2 * p][0] = r0; b[2 * p][1] = r1;
                b[2 * p + 1][0] = r2; b[2 * p + 1][1] = r3;
            }
            #pragma unroll
            for (int mi = 0; mi < 2; mi++)
                #pragma unroll
                for (int ni = 0; ni < 8; ni++)
                    mma_fp16(acc[mi][ni], a[mi], b[ni]);
        }
    }
}

__device__ __forceinline__ void gemm_setup_frags(GemmCtx& g, int lane, int warpM, int warpN) {
    const int aRowL = lane & 15;
    g.aHalf = (uint32_t)((lane >> 4) << 4);
    #pragma unroll
    for (int mi = 0; mi < 2; mi++) {
        int r = warpM * 32 + mi * 16 + aRowL;
        g.aRowOff[mi] = r * 128;
        g.aXor[mi] = (r & 7) << 4;
    }
    const int bRowL = (lane & 7) + ((lane >> 4) << 3);
    g.bHalf = (uint32_t)(((lane >> 3) & 1) << 4);
    #pragma unroll
    for (int p = 0; p < 4; p++) {
        int r = warpN * 64 + p * 16 + bRowL;
        g.bRowOff[p] = r * 128;
        g.bXor[p] = (r & 7) << 4;
    }
}

// ---- Dual-problem GEMM: two independent C = relu?(A@B^T + bias) problems
// sharing N; blockIdx.y < M0/128 -> problem 0, else problem 1. fp16 out.
template <bool RELU>
__global__ __launch_bounds__(256, 2) void gemm_dual(
    const __half* __restrict__ A0, const __half* __restrict__ B0,
    const float* __restrict__ bias0, __half* __restrict__ C0, int M0, int K0,
    const __half* __restrict__ A1, const __half* __restrict__ B1,
    const float* __restrict__ bias1, __half* __restrict__ C1, int K1, int N)
{
    extern __shared__ char smem[];
    const int tid = threadIdx.x;
    const int lane = tid & 31;
    const int wid = tid >> 5;
    const int warpM = wid & 3;
    const int warpN = wid >> 2;

    const __half *A, *B; const float* bias; __half* C; int K, rowBase;
    const int yb = M0 / 128;
    if ((int)blockIdx.y < yb) {
        A = A0; B = B0; bias = bias0; C = C0; K = K0;
        rowBase = blockIdx.y * 128;
    } else {
        A = A1; B = B1; bias = bias1; C = C1; K = K1;
        rowBase = (blockIdx.y - yb) * 128;
    }
    const int colBase = blockIdx.x * 128;

    GemmCtx g;
    g.sbase = smem_u32(smem);
    g.tid = tid;
    g.stride = (size_t)K * 2;
    g.Ab = (const char*)A + (size_t)rowBase * g.stride;
    g.Bb = (const char*)B + (size_t)colBase * g.stride;
    g.T = K / 64;
    gemm_setup_frags(g, lane, warpM, warpN);

    float acc[2][8][4];
    #pragma unroll
    for (int mi = 0; mi < 2; mi++)
        #pragma unroll
        for (int ni = 0; ni < 8; ni++)
            #pragma unroll
            for (int u = 0; u < 4; u++) acc[mi][ni][u] = 0.0f;

    gemm_mainloop(g, acc);

    const int orow0 = rowBase + warpM * 32;
    const int ocol0 = colBase + warpN * 64;
    const int qr = lane >> 2;
    const int qc = (lane & 3) << 1;

    #pragma unroll
    for (int mi = 0; mi < 2; mi++) {
        const int r0 = orow0 + mi * 16 + qr;
        #pragma unroll
        for (int ni = 0; ni < 8; ni++) {
            const int cc = ocol0 + ni * 8 + qc;
            const float b0 = bias[cc];
            const float b1 = bias[cc + 1];
            float v0 = acc[mi][ni][0] + b0;
            float v1 = acc[mi][ni][1] + b1;
            float v2 = acc[mi][ni][2] + b0;
            float v3 = acc[mi][ni][3] + b1;
            if (RELU) {
                v0 = fmaxf(v0, 0.0f); v1 = fmaxf(v1, 0.0f);
                v2 = fmaxf(v2, 0.0f); v3 = fmaxf(v3, 0.0f);
            }
            *(__half2*)(C + (size_t)r0 * N + cc)       = __floats2half2_rn(v0, v1);
            *(__half2*)(C + (size_t)(r0 + 8) * N + cc) = __floats2half2_rn(v2, v3);
        }
    }
}

// ---- Similarity GEMM: fp32 out, epilogue scale invRow[r]*invCol[c]/temp.
__global__ __launch_bounds__(256, 2) void gemm_sim(
    const __half* __restrict__ A, const __half* __restrict__ B,
    const float* __restrict__ tempPtr,
    const float* __restrict__ invRow, const float* __restrict__ invCol,
    float* __restrict__ C, int M, int N, int K)
{
    extern __shared__ char smem[];
    const int tid = threadIdx.x;
    const int lane = tid & 31;
    const int wid = tid >> 5;
    const int warpM = wid & 3;
    const int warpN = wid >> 2;

    const int rowBase = blockIdx.y * 128;
    const int colBase = blockIdx.x * 128;

    GemmCtx g;
    g.sbase = smem_u32(smem);
    g.tid = tid;
    g.stride = (size_t)K * 2;
    g.Ab = (const char*)A + (size_t)rowBase * g.stride;
    g.Bb = (const char*)B + (size_t)colBase * g.stride;
    g.T = K / 64;
    gemm_setup_frags(g, lane, warpM, warpN);

    float acc[2][8][4];
    #pragma unroll
    for (int mi = 0; mi < 2; mi++)
        #pragma unroll
        for (int ni = 0; ni < 8; ni++)
            #pragma unroll
            for (int u = 0; u < 4; u++) acc[mi][ni][u] = 0.0f;

    gemm_mainloop(g, acc);

    const float alpha = 1.0f / (*tempPtr);
    const int orow0 = rowBase + warpM * 32;
    const int ocol0 = colBase + warpN * 64;
    const int qr = lane >> 2;
    const int qc = (lane & 3) << 1;

    #pragma unroll
    for (int mi = 0; mi < 2; mi++) {
        const int r0 = orow0 + mi * 16 + qr;
        const float ri0 = invRow[r0] * alpha;
        const float ri1 = invRow[r0 + 8] * alpha;
        #pragma unroll
        for (int ni = 0; ni < 8; ni++) {
            const int cc = ocol0 + ni * 8 + qc;
            const float ci0 = invCol[cc];
            const float ci1 = invCol[cc + 1];
            float2 o0 = {acc[mi][ni][0] * ri0 * ci0, acc[mi][ni][1] * ri0 * ci1};
            float2 o1 = {acc[mi][ni][2] * ri1 * ci0, acc[mi][ni][3] * ri1 * ci1};
            *(float2*)(C + (size_t)r0 * N + cc) = o0;
            *(float2*)(C + (size_t)(r0 + 8) * N + cc) = o1;
        }
    }
}

// ======================= host wiring ========================================
extern "C" void kernel_launch(void* const* d_in, const int* in_sizes, int n_in,
                              void* d_out, int out_size)
{
    const float* molecule = (const float*)d_in[0];
    const float* protein  = (const float*)d_in[1];
    const float* Wm1 = (const float*)d_in[2];
    const float* bm1 = (const float*)d_in[3];
    const float* Wm2 = (const float*)d_in[4];
    const float* bm2 = (const float*)d_in[5];
    const float* Wp1 = (const float*)d_in[6];
    const float* bp1 = (const float*)d_in[7];
    const float* Wp2 = (const float*)d_in[8];
    const float* bp2 = (const float*)d_in[9];
    const float* temp = (const float*)d_in[10];
    float* out = (float*)d_out;

    const int D     = in_sizes[3];          // 1024
    const int MOLD  = in_sizes[2] / D;      // 768
    const int PROTD = in_sizes[6] / D;      // 1280
    const int Nmol  = in_sizes[0] / MOLD;   // 4096
    const int Mprot = in_sizes[1] / PROTD;  // 8192

    __half *molA, *Wm1B, *Wm2B, *protA, *Wp1B, *Wp2B, *HmA, *HpA, *MPu, *PPu;
    float *invM, *invP;
    cudaGetSymbolAddress((void**)&molA,  g_molA);
    cudaGetSymbolAddress((void**)&Wm1B,  g_Wm1B);
    cudaGetSymbolAddress((void**)&Wm2B,  g_Wm2B);
    cudaGetSymbolAddress((void**)&protA, g_protA);
    cudaGetSymbolAddress((void**)&Wp1B,  g_Wp1B);
    cudaGetSymbolAddress((void**)&Wp2B,  g_Wp2B);
    cudaGetSymbolAddress((void**)&HmA,   g_HmA);
    cudaGetSymbolAddress((void**)&HpA,   g_HpA);
    cudaGetSymbolAddress((void**)&MPu,   g_MPu);
    cudaGetSymbolAddress((void**)&PPu,   g_PPu);
    cudaGetSymbolAddress((void**)&invM,  g_invM);
    cudaGetSymbolAddress((void**)&invP,  g_invP);

    cudaFuncSetAttribute(gemm_dual<true>,
                         cudaFuncAttributeMaxDynamicSharedMemorySize, GSMEM_TOTAL);
    cudaFuncSetAttribute(gemm_dual<false>,
                         cudaFuncAttributeMaxDynamicSharedMemorySize, GSMEM_TOTAL);
    cudaFuncSetAttribute(gemm_sim,
                         cudaFuncAttributeMaxDynamicSharedMemorySize, GSMEM_TOTAL);

    const dim3 blk256(256);

    // Launch 0: ONE fused convert for all six fp32->fp16 tensors.
    const int c0 = D * MOLD / 4;
    const int c1 = D * D / 4;
    const int c2 = D * PROTD / 4;
    const int c3 = D * D / 4;
    const int c4 = Nmol * MOLD / 4;
    const int c5 = Mprot * PROTD / 4;
    const int ctot = c0 + c1 + c2 + c3 + c4 + c5;
    tofp16_multi<<<(ctot + 255) / 256, blk256>>>(
        Wm1, Wm1B, c0, Wm2, Wm2B, c1, Wp1, Wp1B, c2,
        Wp2, Wp2B, c3, molecule, molA, c4, protein, protA, c5);

    // Launch 1: layer-1 for BOTH branches (mol rows first, then prot rows).
    gemm_dual<true><<<dim3(D / 128, (Nmol + Mprot) / 128), blk256, GSMEM_TOTAL>>>(
        molA, Wm1B, bm1, HmA, Nmol, MOLD,
        protA, Wp1B, bp1, HpA, PROTD, D);

    // Launch 2: layer-2 for BOTH branches.
    gemm_dual<false><<<dim3(D / 128, (Nmol + Mprot) / 128), blk256, GSMEM_TOTAL>>>(
        HmA, Wm2B, bm2, MPu, Nmol, D,
        HpA, Wp2B, bp2, PPu, D, D);

    // Launch 3: inverse norms for both projections.
    rowinv_dual<<<(Nmol + Mprot) / 8, blk256>>>(MPu, invM, Nmol, PPu, invP, D);

    // Launch 4: similarity out[i,j] = (PPu_i . MPu_j) * invP[i]*invM[j] / temp.
    gemm_sim<<<dim3(Nmol / 128, Mprot / 128), blk256, GSMEM_TOTAL>>>(
        PPu, MPu, temp, invP, invM, out, Mprot, Nmol, D);
}

// round 17
// speedup vs baseline: 1.2269x; 1.0053x over previous
#include <cuda_runtime.h>
#include <cuda_fp16.h>
#include <cstdint>

// ----------------------------------------------------------------------------
// Coembedding via warp-level plain-fp16 mma.sync (fp32 accumulate).
// R16: 391us (wave-packed dual-problem GEMMs). GEMM pinned at ~330 TF/s
// (legacy-HMMA ceiling; invariant across 3 geometry/occupancy configs).
// This round removes the rowinv pass: the L2 dual GEMM epilogue emits
// DETERMINISTIC per-tile sum-of-squares partials (fixed-order smem reduction,
// no float atomics), and the similarity kernel folds them into invRow/invCol
// in its prologue. Launches: convert, L1-dual, L2-dual(+partials), sim.
// Shapes: N=4096, M=8192, MOL=768, PROT=1280, D=1024.
// ----------------------------------------------------------------------------

// ======================= PTX helpers (compute_100-safe) =====================
__device__ __forceinline__ uint32_t smem_u32(const void* p) {
    uint32_t a;
    asm("{ .reg .u64 t; cvta.to.shared.u64 t, %1; cvt.u32.u64 %0, t; }"
        : "=r"(a) : "l"(p));
    return a;
}
__device__ __forceinline__ void cp_async16(uint32_t dst, const void* src) {
    asm volatile("cp.async.cg.shared.global [%0], [%1], 16;\n" :: "r"(dst), "l"(src));
}
__device__ __forceinline__ void cp_commit() {
    asm volatile("cp.async.commit_group;\n");
}
template <int N> __device__ __forceinline__ void cp_wait() {
    asm volatile("cp.async.wait_group %0;\n" :: "n"(N));
}
__device__ __forceinline__ void ldsm_x4(uint32_t& r0, uint32_t& r1,
                                        uint32_t& r2, uint32_t& r3, uint32_t addr) {
    asm volatile("ldmatrix.sync.aligned.m8n8.x4.shared.b16 {%0,%1,%2,%3}, [%4];"
                 : "=r"(r0), "=r"(r1), "=r"(r2), "=r"(r3) : "r"(addr));
}
__device__ __forceinline__ void mma_fp16(float* c, const uint32_t* a, const uint32_t* b) {
    asm volatile(
        "mma.sync.aligned.m16n8k16.row.col.f32.f16.f16.f32 "
        "{%0,%1,%2,%3}, {%4,%5,%6,%7}, {%8,%9}, {%0,%1,%2,%3};"
        : "+f"(c[0]), "+f"(c[1]), "+f"(c[2]), "+f"(c[3])
        : "r"(a[0]), "r"(a[1]), "r"(a[2]), "r"(a[3]), "r"(b[0]), "r"(b[1]));
}

// ======================= scratch (allocation-free rule) =====================
__device__ __half g_molA [4096u * 768u];
__device__ __half g_Wm1B [1024u * 768u];
__device__ __half g_Wm2B [1024u * 1024u];
__device__ __half g_protA[8192u * 1280u];
__device__ __half g_Wp1B [1024u * 1280u];
__device__ __half g_Wp2B [1024u * 1024u];
__device__ __half g_HmA  [4096u * 1024u];
__device__ __half g_HpA  [8192u * 1024u];
__device__ __half g_MPu  [4096u * 1024u];   // unnormalized mol projection (fp16)
__device__ __half g_PPu  [8192u * 1024u];   // unnormalized prot projection (fp16)
__device__ float g_partM[4096u * 8u];       // per-tile sum-of-squares partials
__device__ float g_partP[8192u * 8u];

// ======================= conversion kernel ==================================
// One launch converts all 6 fp32 tensors to fp16 (segmented flat index, float4).
__global__ __launch_bounds__(256) void tofp16_multi(
    const float* __restrict__ s0, __half* __restrict__ d0, int n0,
    const float* __restrict__ s1, __half* __restrict__ d1, int n1,
    const float* __restrict__ s2, __half* __restrict__ d2, int n2,
    const float* __restrict__ s3, __half* __restrict__ d3, int n3,
    const float* __restrict__ s4, __half* __restrict__ d4, int n4c,
    const float* __restrict__ s5, __half* __restrict__ d5, int n5)
{
    int i = blockIdx.x * 256 + threadIdx.x;
    const float* s; __half* d;
    if      (i < n0)                      { s = s0; d = d0; }
    else if ((i -= n0) < n1)              { s = s1; d = d1; }
    else if ((i -= n1) < n2)              { s = s2; d = d2; }
    else if ((i -= n2) < n3)              { s = s3; d = d3; }
    else if ((i -= n3) < n4c)             { s = s4; d = d4; }
    else if ((i -= n4c) < n5)             { s = s5; d = d5; }
    else return;
    float4 v = ((const float4*)s)[i];
    ((__half2*)d)[2 * i]     = __floats2half2_rn(v.x, v.y);
    ((__half2*)d)[2 * i + 1] = __floats2half2_rn(v.z, v.w);
}

// ======================= mma.sync fp16 GEMM core ============================
#define TILE_B   16384                 // one operand tile: 128 rows x 128 B
#define STAGE_B  (2 * TILE_B)          // A + B
#define GSMEM_GEMM (3 * STAGE_B)       // 98304 B (stage buffers)
#define GSMEM_SIM  (GSMEM_GEMM + 1024) // + invRow/invCol park (256 floats)

struct GemmCtx {
    const char* Ab; const char* Bb; size_t stride; int T;
    uint32_t sbase;
    uint32_t aRowOff[2], aXor[2], bRowOff[4], bXor[4];
    uint32_t aHalf, bHalf;
    int tid;
};

__device__ __forceinline__ void gemm_mainloop(GemmCtx& g, float acc[2][8][4]) {
    auto load_tile = [&](int t, int s) {
        const uint32_t sA = g.sbase + s * STAGE_B;
        const uint32_t sB = sA + TILE_B;
        const size_t kb = (size_t)t * 128;
        #pragma unroll
        for (int i = 0; i < 4; i++) {
            int id = g.tid + i * 256;
            int row = id >> 3;
            int c = (id & 7) << 4;
            uint32_t doff = row * 128 + (c ^ ((row & 7) << 4));
            cp_async16(sA + doff, g.Ab + (size_t)row * g.stride + kb + c);
            cp_async16(sB + doff, g.Bb + (size_t)row * g.stride + kb + c);
        }
        cp_commit();
    };

    load_tile(0, 0);
    load_tile(1, 1);

    for (int t = 0; t < g.T; t++) {
        cp_wait<1>();
        __syncthreads();
        if (t + 2 < g.T) load_tile(t + 2, (t + 2) % 3);
        else             cp_commit();

        const uint32_t sA = g.sbase + (t % 3) * STAGE_B;
        const uint32_t sB = sA + TILE_B;

        #pragma unroll
        for (int ks = 0; ks < 4; ks++) {
            const uint32_t kA = ks * 32 + g.aHalf;
            const uint32_t kB = ks * 32 + g.bHalf;
            uint32_t a[2][4];
            uint32_t b[8][2];
            #pragma unroll
            for (int mi = 0; mi < 2; mi++)
                ldsm_x4(a[mi][0], a[mi][1], a[mi][2], a[mi][3],
                        sA + g.aRowOff[mi] + (kA ^ g.aXor[mi]));
            #pragma unroll
            for (int p = 0; p < 4; p++) {
                uint32_t r0, r1, r2, r3;
                ldsm_x4(r0, r1, r2, r3, sB + g.bRowOff[p] + (kB ^ g.bXor[p]));
                b[2 * p][0] = r0; b[2 * p][1] = r1;
                b[2 * p + 1][0] = r2; b[2 * p + 1][1] = r3;
            }
            #pragma unroll
            for (int mi = 0; mi < 2; mi++)
                #pragma unroll
                for (int ni = 0; ni < 8; ni++)
                    mma_fp16(acc[mi][ni], a[mi], b[ni]);
        }
    }
}

__device__ __forceinline__ void gemm_setup_frags(GemmCtx& g, int lane, int warpM, int warpN) {
    const int aRowL = lane & 15;
    g.aHalf = (uint32_t)((lane >> 4) << 4);
    #pragma unroll
    for (int mi = 0; mi < 2; mi++) {
        int r = warpM * 32 + mi * 16 + aRowL;
        g.aRowOff[mi] = r * 128;
        g.aXor[mi] = (r & 7) << 4;
    }
    const int bRowL = (lane & 7) + ((lane >> 4) << 3);
    g.bHalf = (uint32_t)(((lane >> 3) & 1) << 4);
    #pragma unroll
    for (int p = 0; p < 4; p++) {
        int r = warpN * 64 + p * 16 + bRowL;
        g.bRowOff[p] = r * 128;
        g.bXor[p] = (r & 7) << 4;
    }
}

// ---- Dual-problem GEMM: two independent C = relu?(A@B^T + bias) problems
// sharing N; blockIdx.y < M0/128 -> problem 0, else problem 1. fp16 out.
// NORM_PART: also emit normPart[row*NT + blockIdx.x] = sum of squares of the
// fp16-rounded outputs in this CTA's 128-column slice (deterministic).
template <bool RELU, bool NORM_PART>
__global__ __launch_bounds__(256, 2) void gemm_dual(
    const __half* __restrict__ A0, const __half* __restrict__ B0,
    const float* __restrict__ bias0, __half* __restrict__ C0,
    float* __restrict__ np0, int M0, int K0,
    const __half* __restrict__ A1, const __half* __restrict__ B1,
    const float* __restrict__ bias1, __half* __restrict__ C1,
    float* __restrict__ np1, int K1, int N)
{
    extern __shared__ char smem[];
    const int tid = threadIdx.x;
    const int lane = tid & 31;
    const int wid = tid >> 5;
    const int warpM = wid & 3;
    const int warpN = wid >> 2;

    const __half *A, *B; const float* bias; __half* C; float* np;
    int K, rowBase;
    const int yb = M0 / 128;
    if ((int)blockIdx.y < yb) {
        A = A0; B = B0; bias = bias0; C = C0; np = np0; K = K0;
        rowBase = blockIdx.y * 128;
    } else {
        A = A1; B = B1; bias = bias1; C = C1; np = np1; K = K1;
        rowBase = (blockIdx.y - yb) * 128;
    }
    const int colBase = blockIdx.x * 128;

    GemmCtx g;
    g.sbase = smem_u32(smem);
    g.tid = tid;
    g.stride = (size_t)K * 2;
    g.Ab = (const char*)A + (size_t)rowBase * g.stride;
    g.Bb = (const char*)B + (size_t)colBase * g.stride;
    g.T = K / 64;
    gemm_setup_frags(g, lane, warpM, warpN);

    float acc[2][8][4];
    #pragma unroll
    for (int mi = 0; mi < 2; mi++)
        #pragma unroll
        for (int ni = 0; ni < 8; ni++)
            #pragma unroll
            for (int u = 0; u < 4; u++) acc[mi][ni][u] = 0.0f;

    gemm_mainloop(g, acc);

    const int orow0 = rowBase + warpM * 32;
    const int ocol0 = colBase + warpN * 64;
    const int qr = lane >> 2;
    const int qc = (lane & 3) << 1;

    float rsum[2][2] = {{0.f, 0.f}, {0.f, 0.f}};   // [mi][row0/row8]

    #pragma unroll
    for (int mi = 0; mi < 2; mi++) {
        const int r0 = orow0 + mi * 16 + qr;
        #pragma unroll
        for (int ni = 0; ni < 8; ni++) {
            const int cc = ocol0 + ni * 8 + qc;
            const float b0 = bias[cc];
            const float b1 = bias[cc + 1];
            float v0 = acc[mi][ni][0] + b0;
            float v1 = acc[mi][ni][1] + b1;
            float v2 = acc[mi][ni][2] + b0;
            float v3 = acc[mi][ni][3] + b1;
            if (RELU) {
                v0 = fmaxf(v0, 0.0f); v1 = fmaxf(v1, 0.0f);
                v2 = fmaxf(v2, 0.0f); v3 = fmaxf(v3, 0.0f);
            }
            __half2 h01 = __floats2half2_rn(v0, v1);
            __half2 h23 = __floats2half2_rn(v2, v3);
            *(__half2*)(C + (size_t)r0 * N + cc)       = h01;
            *(__half2*)(C + (size_t)(r0 + 8) * N + cc) = h23;
            if (NORM_PART) {
                float f0 = __low2float(h01), f1 = __high2float(h01);
                float f2 = __low2float(h23), f3 = __high2float(h23);
                rsum[mi][0] = fmaf(f0, f0, fmaf(f1, f1, rsum[mi][0]));
                rsum[mi][1] = fmaf(f2, f2, fmaf(f3, f3, rsum[mi][1]));
            }
        }
    }

    if (NORM_PART) {
        // Deterministic reduction: 8 contributors per row, fixed slot order.
        float* psum = (float*)smem;                 // stages are dead now...
        __syncthreads();                            // ...after ALL warps finish
        const int cIdx = warpN * 4 + (lane & 3);    // 0..7
        #pragma unroll
        for (int mi = 0; mi < 2; mi++) {
            const int lr0 = warpM * 32 + mi * 16 + qr;
            psum[lr0 * 8 + cIdx]       = rsum[mi][0];
            psum[(lr0 + 8) * 8 + cIdx] = rsum[mi][1];
        }
        __syncthreads();
        if (tid < 128) {
            float s = 0.0f;
            #pragma unroll
            for (int j = 0; j < 8; j++) s += psum[tid * 8 + j];
            np[(size_t)(rowBase + tid) * 8 + blockIdx.x] = s;
        }
    }
}

// ---- Similarity GEMM: fp32 out; prologue folds norm partials into
// invRow/invCol (smem), epilogue scales by invRow[r]*invCol[c]/temp.
__global__ __launch_bounds__(256, 2) void gemm_sim(
    const __half* __restrict__ A, const __half* __restrict__ B,
    const float* __restrict__ tempPtr,
    const float* __restrict__ npRow, const float* __restrict__ npCol,
    float* __restrict__ C, int M, int N, int K)
{
    extern __shared__ char smem[];
    const int tid = threadIdx.x;
    const int lane = tid & 31;
    const int wid = tid >> 5;
    const int warpM = wid & 3;
    const int warpN = wid >> 2;

    const int rowBase = blockIdx.y * 128;
    const int colBase = blockIdx.x * 128;

    // Prologue: invRow for this CTA's 128 rows (tid<128), invCol (tid>=128).
    float* invS = (float*)(smem + GSMEM_GEMM);      // [0:128)=row, [128:256)=col
    {
        const float* np = (tid < 128) ? npRow : npCol;
        const int base = (tid < 128) ? rowBase : colBase;
        const int idx = base + (tid & 127);
        float s = 0.0f;
        #pragma unroll
        for (int j = 0; j < 8; j++) s += np[(size_t)idx * 8 + j];
        invS[tid] = 1.0f / fmaxf(sqrtf(s), 1e-8f);
    }
    // Visibility of invS before epilogue reads: guaranteed by the mainloop's
    // internal __syncthreads() (T >= 1).

    GemmCtx g;
    g.sbase = smem_u32(smem);
    g.tid = tid;
    g.stride = (size_t)K * 2;
    g.Ab = (const char*)A + (size_t)rowBase * g.stride;
    g.Bb = (const char*)B + (size_t)colBase * g.stride;
    g.T = K / 64;
    gemm_setup_frags(g, lane, warpM, warpN);

    float acc[2][8][4];
    #pragma unroll
    for (int mi = 0; mi < 2; mi++)
        #pragma unroll
        for (int ni = 0; ni < 8; ni++)
            #pragma unroll
            for (int u = 0; u < 4; u++) acc[mi][ni][u] = 0.0f;

    gemm_mainloop(g, acc);

    const float alpha = 1.0f / (*tempPtr);
    const int orow0 = warpM * 32;                   // CTA-local row
    const int ocol0 = warpN * 64;                   // CTA-local col
    const int qr = lane >> 2;
    const int qc = (lane & 3) << 1;

    #pragma unroll
    for (int mi = 0; mi < 2; mi++) {
        const int lr0 = orow0 + mi * 16 + qr;
        const float ri0 = invS[lr0] * alpha;
        const float ri1 = invS[lr0 + 8] * alpha;
        #pragma unroll
        for (int ni = 0; ni < 8; ni++) {
            const int lc = ocol0 + ni * 8 + qc;
            const float ci0 = invS[128 + lc];
            const float ci1 = invS[128 + lc + 1];
            const int r0 = rowBase + lr0;
            const int cc = colBase + lc;
            float2 o0 = {acc[mi][ni][0] * ri0 * ci0, acc[mi][ni][1] * ri0 * ci1};
            float2 o1 = {acc[mi][ni][2] * ri1 * ci0, acc[mi][ni][3] * ri1 * ci1};
            *(float2*)(C + (size_t)r0 * N + cc) = o0;
            *(float2*)(C + (size_t)(r0 + 8) * N + cc) = o1;
        }
    }
}

// ======================= host wiring ========================================
extern "C" void kernel_launch(void* const* d_in, const int* in_sizes, int n_in,
                              void* d_out, int out_size)
{
    const float* molecule = (const float*)d_in[0];
    const float* protein  = (const float*)d_in[1];
    const float* Wm1 = (const float*)d_in[2];
    const float* bm1 = (const float*)d_in[3];
    const float* Wm2 = (const float*)d_in[4];
    const float* bm2 = (const float*)d_in[5];
    const float* Wp1 = (const float*)d_in[6];
    const float* bp1 = (const float*)d_in[7];
    const float* Wp2 = (const float*)d_in[8];
    const float* bp2 = (const float*)d_in[9];
    const float* temp = (const float*)d_in[10];
    float* out = (float*)d_out;

    const int D     = in_sizes[3];          // 1024
    const int MOLD  = in_sizes[2] / D;      // 768
    const int PROTD = in_sizes[6] / D;      // 1280
    const int Nmol  = in_sizes[0] / MOLD;   // 4096
    const int Mprot = in_sizes[1] / PROTD;  // 8192

    __half *molA, *Wm1B, *Wm2B, *protA, *Wp1B, *Wp2B, *HmA, *HpA, *MPu, *PPu;
    float *partM, *partP;
    cudaGetSymbolAddress((void**)&molA,  g_molA);
    cudaGetSymbolAddress((void**)&Wm1B,  g_Wm1B);
    cudaGetSymbolAddress((void**)&Wm2B,  g_Wm2B);
    cudaGetSymbolAddress((void**)&protA, g_protA);
    cudaGetSymbolAddress((void**)&Wp1B,  g_Wp1B);
    cudaGetSymbolAddress((void**)&Wp2B,  g_Wp2B);
    cudaGetSymbolAddress((void**)&HmA,   g_HmA);
    cudaGetSymbolAddress((void**)&HpA,   g_HpA);
    cudaGetSymbolAddress((void**)&MPu,   g_MPu);
    cudaGetSymbolAddress((void**)&PPu,   g_PPu);
    cudaGetSymbolAddress((void**)&partM, g_partM);
    cudaGetSymbolAddress((void**)&partP, g_partP);

    cudaFuncSetAttribute(gemm_dual<true,  false>,
                         cudaFuncAttributeMaxDynamicSharedMemorySize, GSMEM_GEMM);
    cudaFuncSetAttribute(gemm_dual<false, true >,
                         cudaFuncAttributeMaxDynamicSharedMemorySize, GSMEM_GEMM);
    cudaFuncSetAttribute(gemm_sim,
                         cudaFuncAttributeMaxDynamicSharedMemorySize, GSMEM_SIM);

    const dim3 blk256(256);

    // Launch 0: ONE fused convert for all six fp32->fp16 tensors.
    const int c0 = D * MOLD / 4;
    const int c1 = D * D / 4;
    const int c2 = D * PROTD / 4;
    const int c3 = D * D / 4;
    const int c4 = Nmol * MOLD / 4;
    const int c5 = Mprot * PROTD / 4;
    const int ctot = c0 + c1 + c2 + c3 + c4 + c5;
    tofp16_multi<<<(ctot + 255) / 256, blk256>>>(
        Wm1, Wm1B, c0, Wm2, Wm2B, c1, Wp1, Wp1B, c2,
        Wp2, Wp2B, c3, molecule, molA, c4, protein, protA, c5);

    // Launch 1: layer-1 for BOTH branches (mol rows first, then prot rows).
    gemm_dual<true, false><<<dim3(D / 128, (Nmol + Mprot) / 128), blk256, GSMEM_GEMM>>>(
        molA, Wm1B, bm1, HmA, nullptr, Nmol, MOLD,
        protA, Wp1B, bp1, HpA, nullptr, PROTD, D);

    // Launch 2: layer-2 for BOTH branches + deterministic norm partials.
    gemm_dual<false, true><<<dim3(D / 128, (Nmol + Mprot) / 128), blk256, GSMEM_GEMM>>>(
        HmA, Wm2B, bm2, MPu, partM, Nmol, D,
        HpA, Wp2B, bp2, PPu, partP, D, D);

    // Launch 3: similarity with fused inv-norm prologue.
    // out[i,j] = (PPu_i . MPu_j) * invP[i] * invM[j] / temp
    gemm_sim<<<dim3(Nmol / 128, Mprot / 128), blk256, GSMEM_SIM>>>(
        PPu, MPu, temp, partP, partM, out, Mprot, Nmol, D);
}